// round 13
// baseline (speedup 1.0000x reference)
#include <cuda_runtime.h>

#define TT   2048
#define DD   64
#define HH   64
#define NG   256
#define WIN  8
#define NWINS (TT / WIN)     // 256
#define RING 32              // xg ring slots (4 windows)
#define WPAD 68              // padded W_ih row stride (272B, 16B-aligned)

// Dynamic SMEM layout (float offsets)
#define WIH_OFF 0                              // [256][WPAD]
#define XGR_OFF (NG * WPAD)                    // [2][RING][NG]  (float2 pairs)
#define XST_OFF (XGR_OFF + 2 * RING * NG)      // [4][2][WIN][DD]
#define HS_OFF  (XST_OFF + 4 * 2 * WIN * DD)   // [2 grp][2 buf][HH]
#define SMEM_FLOATS (HS_OFF + 2 * 2 * HH)
#define SMEM_BYTES  (SMEM_FLOATS * 4)          // 152,576 B

__device__ __forceinline__ unsigned long long ffma2(unsigned long long a,
                                                    unsigned long long b,
                                                    unsigned long long c) {
    unsigned long long d;
    asm("fma.rn.f32x2 %0, %1, %2, %3;" : "=l"(d) : "l"(a), "l"(b), "l"(c));
    return d;
}
__device__ __forceinline__ float red2(unsigned long long v) {
    float lo, hi;
    asm("mov.b64 {%0, %1}, %2;" : "=f"(lo), "=f"(hi) : "l"(v));
    return lo + hi;
}
__device__ __forceinline__ float tanh_ap(float x) {
    float y;
    asm("tanh.approx.f32 %0, %1;" : "=f"(y) : "f"(x));
    return y;
}

// ---------------------------------------------------------------------------
// grid=128, block=320:
//   tid   0..127 : rec group A — batch 2*bid,   own bar.sync 1,128 per step
//   tid 128..255 : rec group B — batch 2*bid+1, own bar.sync 2,128 per step
//   tid 256..319 : producer — xg = bias + W_ih.x for both batches, 3 windows
//                  ahead, W_ih from padded SMEM, 4 gates per thread.
// Groups drift independently; __syncthreads() once per 8-step window.
// ---------------------------------------------------------------------------
__global__ void __launch_bounds__(320, 1)
lstm_ws2(const float* __restrict__ x, const float* __restrict__ w_ih,
         const float* __restrict__ w_hh, const float* __restrict__ b_ih,
         const float* __restrict__ b_hh, const float* __restrict__ fc_w,
         const float* __restrict__ fc_b, float* __restrict__ out)
{
    extern __shared__ __align__(16) float sm[];
    float* Ws  = sm + WIH_OFF;
    float* XGR = sm + XGR_OFF;
    float* XST = sm + XST_OFF;
    float* HS  = sm + HS_OFF;

    const int tid = threadIdx.x;
    const int b0  = blockIdx.x * 2;
    const bool is_rec = (tid < 256);

    // ---------------- prologue: stage W_ih (padded) and x windows 0..3 ----
    for (int idx = tid; idx < NG * 16; idx += 320) {       // 4096 float4
        int row = idx >> 4, q = idx & 15;
        *(float4*)(Ws + row * WPAD + q * 4) =
            ((const float4*)(w_ih + (size_t)row * DD))[q];
    }
    for (int idx = tid; idx < 4 * 256; idx += 320) {       // 1024 float4
        int win = idx >> 8, wi = idx & 255;
        int bb = wi >> 7, rem = wi & 127, tq = rem >> 4, q = rem & 15;
        float4 v = ((const float4*)(x +
                    ((size_t)(b0 + bb) * TT + win * WIN + tq) * DD))[q];
        ((float4*)(XST + win * (2 * WIN * DD)))[wi] = v;
    }
    __syncthreads();

    // ---------------- per-role state ----------------
    int grp = 0, lt = 0, u = 0, role = 0, ga = 0, gb = 0, barid = 1;
    ulonglong2 wa[16], wb[16];
    float kb = 0.f, sc = 0.f, off = 0.f;

    int pt = tid - 256;                 // producer thread 0..63
    float bp0 = 0.f, bp1 = 0.f, bp2 = 0.f, bp3 = 0.f;

    if (is_rec) {
        grp = tid >> 7; lt = tid & 127;
        u = lt >> 1; role = lt & 1;
        ga = u + 64 * role; gb = ga + 128;
        barid = grp + 1;
        const ulonglong2* pwa = (const ulonglong2*)(w_hh + ga * HH);
        const ulonglong2* pwb = (const ulonglong2*)(w_hh + gb * HH);
#pragma unroll
        for (int j = 0; j < 16; ++j) { wa[j] = pwa[j]; wb[j] = pwb[j]; }
        kb  = role ? 0.5f : 1.f;
        sc  = role ? 0.5f : 1.f;
        off = role ? 0.5f : 0.f;
        if (lt < 64) {
            HS[grp * 128 + lt] = 0.f;
            HS[grp * 128 + 64 + lt] = 0.f;
        }
    } else {
        bp0 = b_ih[pt]       + b_hh[pt];
        bp1 = b_ih[pt + 64]  + b_hh[pt + 64];
        bp2 = b_ih[pt + 128] + b_hh[pt + 128];
        bp3 = b_ih[pt + 192] + b_hh[pt + 192];
    }
    __syncthreads();

    float c = 0.f;          // rec cell state
    float2 cur;             // rec xg prefetch

    // w = -3..-1: producer computes windows 0..2 while rec idles at the join
    for (int w = -3; w < NWINS; ++w) {
        if (is_rec) {
            if (w >= 0) {
                float* hsg = HS + grp * 128;
                if (w == 0)
                    cur = ((const float2*)(XGR + grp * (RING * NG)))[ga];
#pragma unroll
                for (int i = 0; i < WIN; ++i) {
                    const int t = w * WIN + i;
                    const ulonglong2* hv =
                        (const ulonglong2*)(hsg + (t & 1) * 64);
                    unsigned long long a0 = 0ull, a1 = 0ull,
                                       c0 = 0ull, c1 = 0ull;
#pragma unroll
                    for (int j = 0; j < 16; ++j) {
                        ulonglong2 h2 = hv[j];
                        a0 = ffma2(wa[j].x, h2.x, a0);
                        a1 = ffma2(wa[j].y, h2.y, a1);
                        c0 = ffma2(wb[j].x, h2.x, c0);
                        c1 = ffma2(wb[j].y, h2.y, c1);
                    }
                    float sa = cur.x + red2(a0) + red2(a1);
                    float sb = cur.y + red2(c0) + red2(c1);

                    // prefetch next step's xg (off the critical chain)
                    float2 nxt = ((const float2*)(XGR + grp * (RING * NG)
                                  + ((t + 1) & (RING - 1)) * NG))[ga];

                    float A  = fmaf(0.5f, tanh_ap(0.5f * sa), 0.5f);
                    float Bv = fmaf(sc, tanh_ap(kb * sb), off);
                    float p  = A * Bv;
                    float send = role ? A : p;
                    float recv = __shfl_xor_sync(0xFFFFFFFFu, send, 1);
                    float cm = role ? A : recv;
                    float cd = role ? recv : p;
                    c = fmaf(cm, c, cd);
                    float th = tanh_ap(c);
                    if (role) hsg[((t + 1) & 1) * 64 + u] = Bv * th;

                    asm volatile("bar.sync %0, 128;" :: "r"(barid));
                    cur = nxt;
                }
            }
        } else {
            // ---------------- producer ----------------
            const int wc = w + 3;          // window to compute
            const int wl = w + 4;          // window to stage (only w>=0)
            float4 r0, r1, r2, r3;
            if (w >= 0 && wl < NWINS) {
#pragma unroll
                for (int k = 0; k < 4; ++k) {
                    int idx = pt + k * 64;
                    int bb = idx >> 7, rem = idx & 127;
                    int tq = rem >> 4, q = rem & 15;
                    float4 v = ((const float4*)(x +
                                ((size_t)(b0 + bb) * TT + wl * WIN + tq) * DD))[q];
                    if (k == 0) r0 = v; else if (k == 1) r1 = v;
                    else if (k == 2) r2 = v; else r3 = v;
                }
            }
            if (wc < NWINS) {
#pragma unroll 1
                for (int bb = 0; bb < 2; ++bb) {
                    unsigned long long aa0[8], aa1[8], aa2[8], aa3[8];
#pragma unroll
                    for (int i = 0; i < 8; ++i)
                        { aa0[i] = 0ull; aa1[i] = 0ull; aa2[i] = 0ull; aa3[i] = 0ull; }
                    const float* xw = XST + ((wc & 3) * 2 + bb) * (WIN * DD);
#pragma unroll 4
                    for (int j = 0; j < 16; ++j) {
                        ulonglong2 w0 = *(const ulonglong2*)(Ws + pt * WPAD + j * 4);
                        ulonglong2 w1 = *(const ulonglong2*)(Ws + (pt + 64) * WPAD + j * 4);
                        ulonglong2 w2 = *(const ulonglong2*)(Ws + (pt + 128) * WPAD + j * 4);
                        ulonglong2 w3 = *(const ulonglong2*)(Ws + (pt + 192) * WPAD + j * 4);
#pragma unroll
                        for (int i = 0; i < 8; ++i) {
                            ulonglong2 xv = *(const ulonglong2*)(xw + i * DD + j * 4);
                            aa0[i] = ffma2(w0.x, xv.x, aa0[i]);
                            aa0[i] = ffma2(w0.y, xv.y, aa0[i]);
                            aa1[i] = ffma2(w1.x, xv.x, aa1[i]);
                            aa1[i] = ffma2(w1.y, xv.y, aa1[i]);
                            aa2[i] = ffma2(w2.x, xv.x, aa2[i]);
                            aa2[i] = ffma2(w2.y, xv.y, aa2[i]);
                            aa3[i] = ffma2(w3.x, xv.x, aa3[i]);
                            aa3[i] = ffma2(w3.y, xv.y, aa3[i]);
                        }
                    }
#pragma unroll
                    for (int i = 0; i < 8; ++i) {
                        int slot = (wc * WIN + i) & (RING - 1);
                        float2* dst = (float2*)(XGR + bb * (RING * NG) + slot * NG);
                        dst[pt]      = make_float2(bp0 + red2(aa0[i]),
                                                   bp2 + red2(aa2[i]));
                        dst[pt + 64] = make_float2(bp1 + red2(aa1[i]),
                                                   bp3 + red2(aa3[i]));
                    }
                }
            }
            if (w >= 0 && wl < NWINS) {
                float4* dst = (float4*)(XST + (wl & 3) * (2 * WIN * DD));
                dst[pt]       = r0;
                dst[pt + 64]  = r1;
                dst[pt + 128] = r2;
                dst[pt + 192] = r3;
            }
        }
        __syncthreads();
    }

    // ---- final FC: out[b, o] = h_last . fc_w[o] + fc_b[o] ----
    if (is_rec && lt < 8) {
        const float* hfin = HS + grp * 128 + (TT & 1) * 64;
        float s = fc_b[lt];
#pragma unroll
        for (int k = 0; k < HH; ++k) s += hfin[k] * fc_w[lt * HH + k];
        out[(b0 + grp) * 8 + lt] = s;
    }
}

extern "C" void kernel_launch(void* const* d_in, const int* in_sizes, int n_in,
                              void* d_out, int out_size) {
    const float* x    = (const float*)d_in[0];
    const float* w_ih = (const float*)d_in[1];
    const float* w_hh = (const float*)d_in[2];
    const float* b_ih = (const float*)d_in[3];
    const float* b_hh = (const float*)d_in[4];
    const float* fc_w = (const float*)d_in[5];
    const float* fc_b = (const float*)d_in[6];
    float* out = (float*)d_out;

    const int B = in_sizes[0] / (TT * DD);   // 256

    static int attr_done = 0;
    if (!attr_done) {
        cudaFuncSetAttribute(lstm_ws2,
                             cudaFuncAttributeMaxDynamicSharedMemorySize,
                             SMEM_BYTES);
        attr_done = 1;
    }
    lstm_ws2<<<B / 2, 320, SMEM_BYTES>>>(x, w_ih, w_hh, b_ih, b_hh,
                                         fc_w, fc_b, out);
}

// round 14
// speedup vs baseline: 1.2508x; 1.2508x over previous
#include <cuda_runtime.h>

#define TT   2048
#define DD   64
#define HH   64
#define NG   256
#define WIN  8
#define NWINS (TT / WIN)     // 256
#define RING 32              // xg ring slots (4 windows)

// Dynamic SMEM (float offsets)
#define XGR_OFF 0                              // [2][RING][NG] (float2-packed)
#define XST_OFF (2 * RING * NG)                // [4][2][WIN][DD]
#define HS_OFF  (XST_OFF + 4 * 2 * WIN * DD)   // [2 grp][2 buf][HH]
#define SMEM_FLOATS (HS_OFF + 2 * 2 * HH)
#define SMEM_BYTES  (SMEM_FLOATS * 4)          // 82,944 B

__device__ __forceinline__ unsigned long long ffma2(unsigned long long a,
                                                    unsigned long long b,
                                                    unsigned long long c) {
    unsigned long long d;
    asm("fma.rn.f32x2 %0, %1, %2, %3;" : "=l"(d) : "l"(a), "l"(b), "l"(c));
    return d;
}
__device__ __forceinline__ float red2(unsigned long long v) {
    float lo, hi;
    asm("mov.b64 {%0, %1}, %2;" : "=f"(lo), "=f"(hi) : "l"(v));
    return lo + hi;
}
__device__ __forceinline__ float tanh_ap(float x) {
    float y;
    asm("tanh.approx.f32 %0, %1;" : "=f"(y) : "f"(x));
    return y;
}

// ---------------------------------------------------------------------------
// grid=128, block=384:
//   tid   0..127 : rec A — batch 2*bid,   1 batch, bar.sync 1,128 per step
//   tid 128..255 : rec B — batch 2*bid+1, 1 batch, bar.sync 2,128 per step
//   tid 256..383 : producer — 4 warps, REGISTER W_ih (2 gates/thread),
//                  xg for both batches 3 windows ahead into the SMEM ring;
//                  x staged GMEM->SMEM 4 windows ahead.
// Rec groups drift independently; __syncthreads() once per 8-step window.
// ---------------------------------------------------------------------------
__global__ void __launch_bounds__(384, 1)
lstm_ws3(const float* __restrict__ x, const float* __restrict__ w_ih,
         const float* __restrict__ w_hh, const float* __restrict__ b_ih,
         const float* __restrict__ b_hh, const float* __restrict__ fc_w,
         const float* __restrict__ fc_b, float* __restrict__ out)
{
    extern __shared__ __align__(16) float sm[];
    float* XGR = sm + XGR_OFF;   // [bb][slot][float2 gate-pair]
    float* XST = sm + XST_OFF;   // [slot4][bb][t'][k]
    float* HS  = sm + HS_OFF;    // [grp][buf][u]

    const int tid = threadIdx.x;
    const int b0  = blockIdx.x * 2;
    const bool is_rec = (tid < 256);

    // ---------------- prologue: stage x windows 0..3 ----------------
    for (int idx = tid; idx < 4 * 256; idx += 384) {       // 1024 float4
        int win = idx >> 8, wi = idx & 255;
        int bb = wi >> 7, rem = wi & 127, tq = rem >> 4, q = rem & 15;
        float4 v = ((const float4*)(x +
                    ((size_t)(b0 + bb) * TT + win * WIN + tq) * DD))[q];
        ((float4*)(XST + win * (2 * WIN * DD)))[wi] = v;
    }

    // ---------------- per-role state ----------------
    int grp = 0, lt = 0, u = 0, role = 0, ga = 0, barid = 1;
    ulonglong2 wa[16], wb[16];           // rec: W_hh rows | prod: W_ih rows
    float kb = 0.f, sc = 0.f, off = 0.f;
    int pt = tid - 256;                  // producer thread 0..127
    float bp0 = 0.f, bp1 = 0.f;

    if (is_rec) {
        grp = tid >> 7; lt = tid & 127;
        u = lt >> 1; role = lt & 1;
        ga = u + 64 * role;
        const int gb = ga + 128;
        barid = grp + 1;
        const ulonglong2* pwa = (const ulonglong2*)(w_hh + ga * HH);
        const ulonglong2* pwb = (const ulonglong2*)(w_hh + gb * HH);
#pragma unroll
        for (int j = 0; j < 16; ++j) { wa[j] = pwa[j]; wb[j] = pwb[j]; }
        kb  = role ? 0.5f : 1.f;
        sc  = role ? 0.5f : 1.f;
        off = role ? 0.5f : 0.f;
        if (lt < 64) {
            HS[grp * 128 + lt] = 0.f;
            HS[grp * 128 + 64 + lt] = 0.f;
        }
    } else {
        const ulonglong2* pa = (const ulonglong2*)(w_ih + (size_t)pt * DD);
        const ulonglong2* pb = (const ulonglong2*)(w_ih + (size_t)(pt + 128) * DD);
#pragma unroll
        for (int j = 0; j < 16; ++j) { wa[j] = pa[j]; wb[j] = pb[j]; }
        bp0 = b_ih[pt]       + b_hh[pt];
        bp1 = b_ih[pt + 128] + b_hh[pt + 128];
    }
    __syncthreads();

    float c = 0.f;      // rec cell state
    float2 cur;         // rec xg prefetch

    // w = -3..-1: producer computes windows 0..2; rec idles at the joins
    for (int w = -3; w < NWINS; ++w) {
        if (is_rec) {
            if (w >= 0) {
                float* hsg = HS + grp * 128;
                const float* xgg = XGR + grp * (RING * NG);
                if (w == 0) cur = ((const float2*)xgg)[ga];
#pragma unroll
                for (int i = 0; i < WIN; ++i) {
                    const int t = w * WIN + i;
                    const ulonglong2* hv =
                        (const ulonglong2*)(hsg + (t & 1) * 64);
                    unsigned long long a0 = 0ull, a1 = 0ull,
                                       c0 = 0ull, c1 = 0ull;
#pragma unroll
                    for (int j = 0; j < 16; ++j) {
                        ulonglong2 h2 = hv[j];
                        a0 = ffma2(wa[j].x, h2.x, a0);
                        a1 = ffma2(wa[j].y, h2.y, a1);
                        c0 = ffma2(wb[j].x, h2.x, c0);
                        c1 = ffma2(wb[j].y, h2.y, c1);
                    }
                    float sa = cur.x + red2(a0) + red2(a1);
                    float sb = cur.y + red2(c0) + red2(c1);

                    // prefetch next step's xg (off the critical chain)
                    float2 nxt = ((const float2*)(xgg +
                                  ((t + 1) & (RING - 1)) * NG))[ga];

                    float A  = fmaf(0.5f, tanh_ap(0.5f * sa), 0.5f);  // i or f
                    float Bv = fmaf(sc, tanh_ap(kb * sb), off);       // g or o
                    float p  = A * Bv;
                    float send = role ? A : p;
                    float recv = __shfl_xor_sync(0xFFFFFFFFu, send, 1);
                    float cm = role ? A : recv;
                    float cd = role ? recv : p;
                    c = fmaf(cm, c, cd);
                    float th = tanh_ap(c);
                    if (role) hsg[((t + 1) & 1) * 64 + u] = Bv * th;

                    asm volatile("bar.sync %0, 128;" :: "r"(barid));
                    cur = nxt;
                }
            }
        } else {
            // ---------------- producer ----------------
            const int wc = w + 3;          // window to compute
            const int wl = w + 4;          // window to stage (w>=0 only)
            float4 r0, r1;
            if (w >= 0 && wl < NWINS) {
                int idx0 = pt, idx1 = pt + 128;
                int bb0 = idx0 >> 7, rem0 = idx0 & 127;
                int bb1 = idx1 >> 7, rem1 = idx1 & 127;
                r0 = ((const float4*)(x + ((size_t)(b0 + bb0) * TT
                        + wl * WIN + (rem0 >> 4)) * DD))[rem0 & 15];
                r1 = ((const float4*)(x + ((size_t)(b0 + bb1) * TT
                        + wl * WIN + (rem1 >> 4)) * DD))[rem1 & 15];
            }
            if (wc < NWINS) {
#pragma unroll 1
                for (int bb = 0; bb < 2; ++bb) {
                    const float* xw = XST + ((wc & 3) * 2 + bb) * (WIN * DD);
                    float2* dst = (float2*)(XGR + bb * (RING * NG));
#pragma unroll 1
                    for (int half = 0; half < 2; ++half) {
                        unsigned long long aa[4], ab[4];
#pragma unroll
                        for (int i = 0; i < 4; ++i) { aa[i] = 0ull; ab[i] = 0ull; }
#pragma unroll 4
                        for (int j = 0; j < 16; ++j) {
                            ulonglong2 wja = wa[j], wjb = wb[j];
#pragma unroll
                            for (int i = 0; i < 4; ++i) {
                                ulonglong2 xv = *(const ulonglong2*)(xw
                                        + (half * 4 + i) * DD + j * 4);
                                aa[i] = ffma2(wja.x, xv.x, aa[i]);
                                aa[i] = ffma2(wja.y, xv.y, aa[i]);
                                ab[i] = ffma2(wjb.x, xv.x, ab[i]);
                                ab[i] = ffma2(wjb.y, xv.y, ab[i]);
                            }
                        }
#pragma unroll
                        for (int i = 0; i < 4; ++i) {
                            int slot = (wc * WIN + half * 4 + i) & (RING - 1);
                            dst[slot * (NG / 2) + pt] =
                                make_float2(bp0 + red2(aa[i]),
                                            bp1 + red2(ab[i]));
                        }
                    }
                }
            }
            if (w >= 0 && wl < NWINS) {
                float4* dst = (float4*)(XST + (wl & 3) * (2 * WIN * DD));
                dst[pt]       = r0;
                dst[pt + 128] = r1;
            }
        }
        __syncthreads();
    }

    // ---- final FC: out[b, o] = h_last . fc_w[o] + fc_b[o] ----
    if (is_rec && lt < 8) {
        const float* hfin = HS + grp * 128 + (TT & 1) * 64;
        float s = fc_b[lt];
#pragma unroll
        for (int k = 0; k < HH; ++k) s += hfin[k] * fc_w[lt * HH + k];
        out[(b0 + grp) * 8 + lt] = s;
    }
}

extern "C" void kernel_launch(void* const* d_in, const int* in_sizes, int n_in,
                              void* d_out, int out_size) {
    const float* x    = (const float*)d_in[0];
    const float* w_ih = (const float*)d_in[1];
    const float* w_hh = (const float*)d_in[2];
    const float* b_ih = (const float*)d_in[3];
    const float* b_hh = (const float*)d_in[4];
    const float* fc_w = (const float*)d_in[5];
    const float* fc_b = (const float*)d_in[6];
    float* out = (float*)d_out;

    const int B = in_sizes[0] / (TT * DD);   // 256

    static int attr_done = 0;
    if (!attr_done) {
        cudaFuncSetAttribute(lstm_ws3,
                             cudaFuncAttributeMaxDynamicSharedMemorySize,
                             SMEM_BYTES);
        attr_done = 1;
    }
    lstm_ws3<<<B / 2, 384, SMEM_BYTES>>>(x, w_ih, w_hh, b_ih, b_hh,
                                         fc_w, fc_b, out);
}

// round 15
// speedup vs baseline: 1.4220x; 1.1369x over previous
#include <cuda_runtime.h>

#define TT   2048
#define DD   64
#define HH   64
#define NG   256
#define WIN  8                 // steps per window
#define NWINS (TT / WIN)       // 256
#define RING 32                // xg ring slots (4 windows)

// Dynamic SMEM layout (floats):
//  XGR: [2][RING][NG]      xg ring per batch (float2-packed gate pairs)
//  XST: [4][2][WIN][DD]    x stage ring (4 windows)
//  HS : [2][2][HH]         h double buffer
#define XGR_OFF 0
#define XST_OFF 16384
#define HS_OFF  (16384 + 4096)
#define SMEM_FLOATS (HS_OFF + 256)
#define SMEM_BYTES  (SMEM_FLOATS * 4)   // 82,944 B

__device__ __forceinline__ unsigned long long ffma2(unsigned long long a,
                                                    unsigned long long b,
                                                    unsigned long long c) {
    unsigned long long d;
    asm("fma.rn.f32x2 %0, %1, %2, %3;" : "=l"(d) : "l"(a), "l"(b), "l"(c));
    return d;
}
__device__ __forceinline__ float red2(unsigned long long v) {
    float lo, hi;
    asm("mov.b64 {%0, %1}, %2;" : "=f"(lo), "=f"(hi) : "l"(v));
    return lo + hi;
}
__device__ __forceinline__ float tanh_ap(float x) {
    float y;
    asm("tanh.approx.f32 %0, %1;" : "=f"(y) : "f"(x));
    return y;
}

// ---------------------------------------------------------------------------
// One fused kernel (R12 skeleton). grid=128, block=256.
//   warps 0-3  (tid 0..127): recurrence for 2 batches, xg from SMEM ring
//                            (float2 pairs, next-step register prefetch),
//                            bar.sync 1,128 per step.
//   warps 4-7  (tid 128..255): producer — xg = bias + W_ih . x for the same
//                            2 batches, 3 windows ahead into the ring;
//                            x staged GMEM->SMEM 4 windows ahead.
//   __syncthreads() once per 8-step window joins the two sides.
// ---------------------------------------------------------------------------
__global__ void __launch_bounds__(256, 1)
lstm_ws(const float* __restrict__ x, const float* __restrict__ w_ih,
        const float* __restrict__ w_hh, const float* __restrict__ b_ih,
        const float* __restrict__ b_hh, const float* __restrict__ fc_w,
        const float* __restrict__ fc_b, float* __restrict__ out)
{
    extern __shared__ __align__(16) float sm[];
    float* XGR = sm + XGR_OFF;   // [bb][slot][float2 gate-pair]
    float* XST = sm + XST_OFF;   // [sslot][bb][t'][k]
    float* HS  = sm + HS_OFF;    // [buf][bb][u]

    const int tid = threadIdx.x;
    const int b0  = blockIdx.x * 2;
    const bool is_rec = (tid < 128);

    // ---------- prologue: cooperatively stage x windows 0..3 ----------
    {
#pragma unroll
        for (int r = 0; r < 4; ++r) {
            int idx = tid + r * 256;            // 0..1023 float4s
            int win = idx >> 8;
            int wi  = idx & 255;
            int bb  = wi >> 7;
            int rem = wi & 127;
            int tq  = rem >> 4;
            int q   = rem & 15;
            float4 v = ((const float4*)(x +
                        ((size_t)(b0 + bb) * TT + win * WIN + tq) * DD))[q];
            ((float4*)(XST + win * (2 * WIN * DD)))[wi] = v;
        }
    }
    __syncthreads();

    // =====================  REC side state  =====================
    int u = 0, role = 0, ga = 0, gb = 0;
    ulonglong2 wa[16], wb[16];
    float kb = 0.f, sc = 0.f, off = 0.f;
    // =====================  PROD side state =====================
    int pt = tid - 128;
    int pga = pt, pgb = pt + 128;
    ulonglong2 wpa[16], wpb[16];
    float bpa = 0.f, bpb = 0.f;

    if (is_rec) {
        u = tid >> 1; role = tid & 1;
        ga = u + 64 * role; gb = ga + 128;
        const ulonglong2* pwa = (const ulonglong2*)(w_hh + ga * HH);
        const ulonglong2* pwb = (const ulonglong2*)(w_hh + gb * HH);
#pragma unroll
        for (int j = 0; j < 16; ++j) { wa[j] = pwa[j]; wb[j] = pwb[j]; }
        kb  = role ? 0.5f : 1.f;
        sc  = role ? 0.5f : 1.f;
        off = role ? 0.5f : 0.f;
        if (tid < 64) {
            HS[tid] = 0.f; HS[64 + tid] = 0.f;
            HS[128 + tid] = 0.f; HS[192 + tid] = 0.f;
        }
    } else {
        const ulonglong2* pa = (const ulonglong2*)(w_ih + (size_t)pga * DD);
        const ulonglong2* pb = (const ulonglong2*)(w_ih + (size_t)pgb * DD);
#pragma unroll
        for (int j = 0; j < 16; ++j) { wpa[j] = pa[j]; wpb[j] = pb[j]; }
        bpa = b_ih[pga] + b_hh[pga];
        bpb = b_ih[pgb] + b_hh[pgb];

        // prologue: compute windows 0,1,2 into the xg ring (float2-packed)
        for (int wc = 0; wc < 3; ++wc) {
            const float* xw = XST + (wc & 3) * (2 * WIN * DD);
#pragma unroll
            for (int bb = 0; bb < 2; ++bb) {
                unsigned long long aa[8], ab[8];
#pragma unroll
                for (int i = 0; i < 8; ++i) { aa[i] = 0ull; ab[i] = 0ull; }
#pragma unroll
                for (int j = 0; j < 16; ++j) {
                    ulonglong2 wja = wpa[j], wjb = wpb[j];
#pragma unroll
                    for (int i = 0; i < 8; ++i) {
                        ulonglong2 xv = *(const ulonglong2*)(xw + bb * WIN * DD
                                                             + i * DD + j * 4);
                        aa[i] = ffma2(wja.x, xv.x, aa[i]);
                        aa[i] = ffma2(wja.y, xv.y, aa[i]);
                        ab[i] = ffma2(wjb.x, xv.x, ab[i]);
                        ab[i] = ffma2(wjb.y, xv.y, ab[i]);
                    }
                }
#pragma unroll
                for (int i = 0; i < 8; ++i) {
                    int slot = (wc * WIN + i) & (RING - 1);
                    ((float2*)(XGR + bb * (RING * NG) + slot * NG))[pga] =
                        make_float2(bpa + red2(aa[i]), bpb + red2(ab[i]));
                }
            }
        }
    }
    __syncthreads();

    float c0s = 0.f, c1s = 0.f;   // rec cell states
    float2 cur0, cur1;            // xg prefetch registers (rec only)
    if (is_rec) {
        cur0 = ((const float2*)XGR)[ga];
        cur1 = ((const float2*)(XGR + RING * NG))[ga];
    }

    for (int w = 0; w < NWINS; ++w) {
        if (is_rec) {
            // ---------------- 8 recurrence steps ----------------
#pragma unroll
            for (int i = 0; i < 8; ++i) {
                const int t = w * WIN + i;

                const ulonglong2* hv0 = (const ulonglong2*)(HS + (t & 1) * 128);
                const ulonglong2* hv1 = hv0 + 16;   // batch 1 (+64 floats)
                unsigned long long A0 = 0ull, A1 = 0ull, C0 = 0ull, C1 = 0ull;
                unsigned long long D0 = 0ull, D1 = 0ull, E0 = 0ull, E1 = 0ull;
#pragma unroll
                for (int j = 0; j < 16; ++j) {
                    ulonglong2 h20 = hv0[j];
                    ulonglong2 h21 = hv1[j];
                    A0 = ffma2(wa[j].x, h20.x, A0);
                    A1 = ffma2(wa[j].y, h20.y, A1);
                    C0 = ffma2(wb[j].x, h20.x, C0);
                    C1 = ffma2(wb[j].y, h20.y, C1);
                    D0 = ffma2(wa[j].x, h21.x, D0);
                    D1 = ffma2(wa[j].y, h21.y, D1);
                    E0 = ffma2(wb[j].x, h21.x, E0);
                    E1 = ffma2(wb[j].y, h21.y, E1);
                }
                float sa0 = cur0.x + red2(A0) + red2(A1);
                float sb0 = cur0.y + red2(C0) + red2(C1);
                float sa1 = cur1.x + red2(D0) + red2(D1);
                float sb1 = cur1.y + red2(E0) + red2(E1);

                // prefetch next step's xg (off the critical chain)
                const int ns = (t + 1) & (RING - 1);
                float2 nx0 = ((const float2*)(XGR + ns * NG))[ga];
                float2 nx1 = ((const float2*)(XGR + RING * NG + ns * NG))[ga];

                float Aq0 = fmaf(0.5f, tanh_ap(0.5f * sa0), 0.5f);
                float Bv0 = fmaf(sc, tanh_ap(kb * sb0), off);
                float pr0 = Aq0 * Bv0;
                float sd0 = role ? Aq0 : pr0;
                float Aq1 = fmaf(0.5f, tanh_ap(0.5f * sa1), 0.5f);
                float Bv1 = fmaf(sc, tanh_ap(kb * sb1), off);
                float pr1 = Aq1 * Bv1;
                float sd1 = role ? Aq1 : pr1;

                float rv0 = __shfl_xor_sync(0xFFFFFFFFu, sd0, 1);
                float rv1 = __shfl_xor_sync(0xFFFFFFFFu, sd1, 1);

                float cm0 = role ? Aq0 : rv0, cd0 = role ? rv0 : pr0;
                float cm1 = role ? Aq1 : rv1, cd1 = role ? rv1 : pr1;
                c0s = fmaf(cm0, c0s, cd0);
                c1s = fmaf(cm1, c1s, cd1);
                float th0 = tanh_ap(c0s);
                float th1 = tanh_ap(c1s);
                if (role) {
                    HS[((t + 1) & 1) * 128 + u]      = Bv0 * th0;
                    HS[((t + 1) & 1) * 128 + 64 + u] = Bv1 * th1;
                }
                asm volatile("bar.sync 1, 128;");
                cur0 = nx0;
                cur1 = nx1;
            }
        } else {
            // ---------------- producer ----------------
            const int wl = w + 4;          // window to stage
            const int wc = w + 3;          // window to compute
            float4 r0, r1;
            if (wl < NWINS) {
                int idx0 = pt, idx1 = pt + 128;
                int bb0 = idx0 >> 7, tq0 = (idx0 & 127) >> 4, q0 = idx0 & 15;
                int bb1 = idx1 >> 7, tq1 = (idx1 & 127) >> 4, q1 = idx1 & 15;
                r0 = ((const float4*)(x + ((size_t)(b0 + bb0) * TT
                                           + wl * WIN + tq0) * DD))[q0];
                r1 = ((const float4*)(x + ((size_t)(b0 + bb1) * TT
                                           + wl * WIN + tq1) * DD))[q1];
            }
            if (wc < NWINS) {
                const float* xw = XST + (wc & 3) * (2 * WIN * DD);
#pragma unroll
                for (int bb = 0; bb < 2; ++bb) {
                    unsigned long long aa[8], ab[8];
#pragma unroll
                    for (int i = 0; i < 8; ++i) { aa[i] = 0ull; ab[i] = 0ull; }
#pragma unroll
                    for (int j = 0; j < 16; ++j) {
                        ulonglong2 wja = wpa[j], wjb = wpb[j];
#pragma unroll
                        for (int i = 0; i < 8; ++i) {
                            ulonglong2 xv = *(const ulonglong2*)(xw
                                            + bb * WIN * DD + i * DD + j * 4);
                            aa[i] = ffma2(wja.x, xv.x, aa[i]);
                            aa[i] = ffma2(wja.y, xv.y, aa[i]);
                            ab[i] = ffma2(wjb.x, xv.x, ab[i]);
                            ab[i] = ffma2(wjb.y, xv.y, ab[i]);
                        }
                    }
#pragma unroll
                    for (int i = 0; i < 8; ++i) {
                        int slot = (wc * WIN + i) & (RING - 1);
                        ((float2*)(XGR + bb * (RING * NG) + slot * NG))[pga] =
                            make_float2(bpa + red2(aa[i]), bpb + red2(ab[i]));
                    }
                }
            }
            if (wl < NWINS) {   // stage into slot wl&3 == w&3 (window w's x is dead)
                float4* dst = (float4*)(XST + (wl & 3) * (2 * WIN * DD));
                dst[pt]       = r0;
                dst[pt + 128] = r1;
            }
        }
        __syncthreads();
    }

    // ---- final FC: out[b, o] = h_last . fc_w[o] + fc_b[o] ----
    if (tid < 16) {
        int bb = tid >> 3, o = tid & 7;
        const float* hfin = HS + (TT & 1) * 128 + bb * 64;
        float s = fc_b[o];
#pragma unroll
        for (int k = 0; k < HH; ++k) s += hfin[k] * fc_w[o * HH + k];
        out[(b0 + bb) * 8 + o] = s;
    }
}

extern "C" void kernel_launch(void* const* d_in, const int* in_sizes, int n_in,
                              void* d_out, int out_size) {
    const float* x    = (const float*)d_in[0];
    const float* w_ih = (const float*)d_in[1];
    const float* w_hh = (const float*)d_in[2];
    const float* b_ih = (const float*)d_in[3];
    const float* b_hh = (const float*)d_in[4];
    const float* fc_w = (const float*)d_in[5];
    const float* fc_b = (const float*)d_in[6];
    float* out = (float*)d_out;

    const int B = in_sizes[0] / (TT * DD);   // 256

    static int attr_done = 0;
    if (!attr_done) {
        cudaFuncSetAttribute(lstm_ws,
                             cudaFuncAttributeMaxDynamicSharedMemorySize,
                             SMEM_BYTES);
        attr_done = 1;
    }
    lstm_ws<<<B / 2, 256, SMEM_BYTES>>>(x, w_ih, w_hh, b_ih, b_hh,
                                        fc_w, fc_b, out);
}